// round 2
// baseline (speedup 1.0000x reference)
#include <cuda_runtime.h>
#include <cuda_bf16.h>

// ---------------------------------------------------------------------------
// Dimensions (fixed by the problem)
// ---------------------------------------------------------------------------
#define Bn    2
#define Hn    256
#define Wd    256
#define Cn    32
#define Pn    8
#define HEADS 8
#define DIMn  32
#define GH    32
#define GW    32
#define Mrows 2048            // B*GH*GW patches
#define K1    2048            // P*P*C
#define F1    16384           // DIM*P*P*HEADS
#define K2    16384           // P*P*HEADS*DIM
#define N2    2048            // DIM*P*P

// ---------------------------------------------------------------------------
// Device scratch (allocation-free rule: __device__ globals)
// ---------------------------------------------------------------------------
__device__ float g_A[Mrows * K1];              // patchified LN1(x)      16 MB
__device__ float g_q[Bn * HEADS * 1024 * DIMn * 64];   // 134 MB each
__device__ float g_k[Bn * HEADS * 1024 * DIMn * 64];
__device__ float g_v[Bn * HEADS * 1024 * DIMn * 64];
__device__ float g_o[Mrows * K2];              // im2col of gated output 134 MB

// ---------------------------------------------------------------------------
// Kernel 1: LN over channels + patchify into A matrix
//   A[(b,gh,gw)][(p0*8+p1)*32 + c] = LN1(x)[b, gh*8+p0, gw*8+p1, c]
// One warp per pixel (32 channels = 32 lanes).
// ---------------------------------------------------------------------------
__global__ __launch_bounds__(256)
void ln1_kernel(const float* __restrict__ x, const float* __restrict__ sc,
                const float* __restrict__ bi)
{
    int lane = threadIdx.x & 31;
    int warp = threadIdx.x >> 5;
    int pix  = blockIdx.x * 8 + warp;            // 0 .. B*H*W-1
    float v  = x[pix * 32 + lane];
    float su = v, sq = v * v;
#pragma unroll
    for (int off = 16; off; off >>= 1) {
        su += __shfl_xor_sync(0xffffffffu, su, off);
        sq += __shfl_xor_sync(0xffffffffu, sq, off);
    }
    float mu  = su * (1.f / 32.f);
    float var = sq * (1.f / 32.f) - mu * mu;
    float y   = (v - mu) * rsqrtf(var + 1e-6f) * sc[lane] + bi[lane];
    int b = pix >> 16;
    int h = (pix >> 8) & 255;
    int w = pix & 255;
    int row = b * 1024 + (h >> 3) * 32 + (w >> 3);
    g_A[row * K1 + ((h & 7) * 8 + (w & 7)) * 32 + lane] = y;
}

// ---------------------------------------------------------------------------
// SGEMM: C = A[M,K] * B[K,N] + bias, fused scatter epilogue.
//  EPI==0 : QKV projection. col f decodes (c,p0,p1,head); dest layout
//           [(b*8+head)*1024+ghgw][c][p0*8+p1]  (contiguous per patch-chan)
//  EPI==1 : output projection. col g decodes (c,p0,p1); dest is final
//           [B,H,W,DIM] with +bias +residual x.
// Tiling: 128x128x16, 256 threads, 8x8 per-thread microtile.
// All dims divide the tile sizes exactly -> no bounds checks.
// ---------------------------------------------------------------------------
template <int EPI>
__global__ __launch_bounds__(256, 2)
void sgemm_k(const float* __restrict__ A, const float* __restrict__ B,
             const float* __restrict__ bias, float* __restrict__ C,
             const float* __restrict__ X, int K, int N)
{
    __shared__ float As[16][132];
    __shared__ float Bs[16][132];

    const int tid = threadIdx.x;
    const int tx = tid & 15, ty = tid >> 4;
    const int rowBase = blockIdx.y * 128;
    const int colBase = blockIdx.x * 128;

    const int ar = tid >> 2;             // 0..63  (A tile row, +64 second)
    const int ak = (tid & 3) * 4;        // k offset within tile
    const int br = tid >> 5;             // 0..7   (B tile k-row, +8 second)
    const int bc = (tid & 31) * 4;       // col offset within tile

    const float* Ap = A + rowBase * K;
    const float* Bp = B + colBase;

    float acc[8][8];
#pragma unroll
    for (int i = 0; i < 8; i++)
#pragma unroll
        for (int j = 0; j < 8; j++) acc[i][j] = 0.f;

    for (int k0 = 0; k0 < K; k0 += 16) {
        float4 a0 = *(const float4*)&Ap[ar * K + k0 + ak];
        float4 a1 = *(const float4*)&Ap[(ar + 64) * K + k0 + ak];
        As[ak + 0][ar] = a0.x; As[ak + 1][ar] = a0.y;
        As[ak + 2][ar] = a0.z; As[ak + 3][ar] = a0.w;
        As[ak + 0][ar + 64] = a1.x; As[ak + 1][ar + 64] = a1.y;
        As[ak + 2][ar + 64] = a1.z; As[ak + 3][ar + 64] = a1.w;
        float4 b0 = *(const float4*)&Bp[(k0 + br) * N + bc];
        float4 b1 = *(const float4*)&Bp[(k0 + br + 8) * N + bc];
        *(float4*)&Bs[br][bc]     = b0;
        *(float4*)&Bs[br + 8][bc] = b1;
        __syncthreads();
#pragma unroll
        for (int kk = 0; kk < 16; kk++) {
            float a[8], b[8];
            *(float4*)&a[0] = *(const float4*)&As[kk][ty * 8];
            *(float4*)&a[4] = *(const float4*)&As[kk][ty * 8 + 4];
            *(float4*)&b[0] = *(const float4*)&Bs[kk][tx * 8];
            *(float4*)&b[4] = *(const float4*)&Bs[kk][tx * 8 + 4];
#pragma unroll
            for (int i = 0; i < 8; i++)
#pragma unroll
                for (int j = 0; j < 8; j++) acc[i][j] += a[i] * b[j];
        }
        __syncthreads();
    }

#pragma unroll
    for (int i = 0; i < 8; i++) {
        int r = rowBase + ty * 8 + i;
        int b_ = r >> 10, ghgw = r & 1023;
#pragma unroll
        for (int j = 0; j < 8; j++) {
            int f = colBase + tx * 8 + j;
            float v = acc[i][j] + bias[f];
            if (EPI == 0) {
                int head = f & 7, p1 = (f >> 3) & 7, p0 = (f >> 6) & 7, c = f >> 9;
                C[(((b_ * 8 + head) * 1024 + ghgw) * 32 + c) * 64 + p0 * 8 + p1] = v;
            } else {
                int gh = ghgw >> 5, gw = ghgw & 31;
                int p1 = f & 7, p0 = (f >> 3) & 7, c = f >> 6;
                int idx = ((b_ * 256 + gh * 8 + p0) * 256 + gw * 8 + p1) * 32 + c;
                C[idx] = v + X[idx];
            }
        }
    }
}

// ---------------------------------------------------------------------------
// Kernel 3: fused 8x8 circular conv (== irfft2(rfft2(q)*rfft2(k)))
//           + LN2 over DIM + gate by V + scatter into im2col of out-proj.
// One block per (b,head,gh,gw): 32 channels x 64 positions.
// Thread layout: warp = p0 (8 warps), lane = c (32 lanes).
// ---------------------------------------------------------------------------
__global__ __launch_bounds__(256)
void fsas_kernel(const float* __restrict__ ln2s, const float* __restrict__ ln2b)
{
    __shared__ float sq[32][65], sk[32][65], sv[32][65], so[32][65];
    __shared__ float smu[64], srv[64];

    int tid  = threadIdx.x;
    int blk  = blockIdx.x;                  // (b*8+head)*1024 + ghgw
    int bh   = blk >> 10, ghgw = blk & 1023;
    int b    = bh >> 3,   head = bh & 7;
    int base = blk * 2048;

    for (int i = tid; i < 2048; i += 256) {
        int c = i >> 6, p = i & 63;
        sq[c][p] = g_q[base + i];
        sk[c][p] = g_k[base + i];
        sv[c][p] = g_v[base + i];
    }
    __syncthreads();

    int c = tid & 31, p0 = tid >> 5;
    float out[8] = {0.f, 0.f, 0.f, 0.f, 0.f, 0.f, 0.f, 0.f};
#pragma unroll
    for (int a0 = 0; a0 < 8; a0++) {
        const float* qr = &sq[c][a0 * 8];
        const float* kr = &sk[c][((p0 - a0) & 7) * 8];
        float kv[8];
#pragma unroll
        for (int t = 0; t < 8; t++) kv[t] = kr[t];
#pragma unroll
        for (int a1 = 0; a1 < 8; a1++) {
            float qa = qr[a1];
#pragma unroll
            for (int p1 = 0; p1 < 8; p1++) out[p1] += qa * kv[(p1 - a1) & 7];
        }
    }
#pragma unroll
    for (int p1 = 0; p1 < 8; p1++) so[c][p0 * 8 + p1] = out[p1];
    __syncthreads();

    if (tid < 64) {                          // LN stats per position over c
        float s = 0.f, s2 = 0.f;
#pragma unroll
        for (int cc = 0; cc < 32; cc++) { float v = so[cc][tid]; s += v; s2 += v * v; }
        float mu  = s * (1.f / 32.f);
        float var = s2 * (1.f / 32.f) - mu * mu;
        smu[tid] = mu;
        srv[tid] = rsqrtf(var + 1e-6f);
    }
    __syncthreads();

    int orow = (b * 1024 + ghgw) * K2 + head * 32;
    for (int i = tid; i < 2048; i += 256) {
        int p = i >> 5, cc = i & 31;
        float val = (so[cc][p] - smu[p]) * srv[p] * ln2s[cc] + ln2b[cc];
        val *= sv[cc][p];
        g_o[orow + p * 256 + cc] = val;      // im2col layout for out-proj GEMM
    }
}

// ---------------------------------------------------------------------------
// Launch
// ---------------------------------------------------------------------------
extern "C" void kernel_launch(void* const* d_in, const int* in_sizes, int n_in,
                              void* d_out, int out_size)
{
    const float* x    = (const float*)d_in[0];
    const float* ln1s = (const float*)d_in[1];
    const float* ln1b = (const float*)d_in[2];
    const float* Wq   = (const float*)d_in[3];
    const float* bq   = (const float*)d_in[4];
    const float* Wk   = (const float*)d_in[5];
    const float* bk   = (const float*)d_in[6];
    const float* Wv   = (const float*)d_in[7];
    const float* bv   = (const float*)d_in[8];
    const float* ln2s = (const float*)d_in[9];
    const float* ln2b = (const float*)d_in[10];
    const float* Wo   = (const float*)d_in[11];
    const float* bo   = (const float*)d_in[12];
    float* out = (float*)d_out;

    float *pA, *pq, *pk, *pv, *po;
    cudaGetSymbolAddress((void**)&pA, g_A);
    cudaGetSymbolAddress((void**)&pq, g_q);
    cudaGetSymbolAddress((void**)&pk, g_k);
    cudaGetSymbolAddress((void**)&pv, g_v);
    cudaGetSymbolAddress((void**)&po, g_o);

    // 1) LN1 + patchify
    ln1_kernel<<<(Bn * Hn * Wd) / 8, 256>>>(x, ln1s, ln1b);

    // 2) Q/K/V projections: [2048x2048] x [2048x16384]
    dim3 g1(F1 / 128, Mrows / 128);
    sgemm_k<0><<<g1, 256>>>(pA, Wq, bq, pq, nullptr, K1, F1);
    sgemm_k<0><<<g1, 256>>>(pA, Wk, bk, pk, nullptr, K1, F1);
    sgemm_k<0><<<g1, 256>>>(pA, Wv, bv, pv, nullptr, K1, F1);

    // 3) circular conv + LN2 + gate + im2col
    fsas_kernel<<<Bn * HEADS * GH * GW, 256>>>(ln2s, ln2b);

    // 4) output projection + bias + residual: [2048x16384] x [16384x2048]
    dim3 g2(N2 / 128, Mrows / 128);
    sgemm_k<1><<<g2, 256>>>(po, Wo, bo, out, x, K2, N2);
}

// round 4
// speedup vs baseline: 2.0183x; 2.0183x over previous
#include <cuda_runtime.h>
#include <cuda_bf16.h>
#include <cstdint>

// ---------------------------------------------------------------------------
// Dimensions
// ---------------------------------------------------------------------------
#define Bn    2
#define Hn    256
#define Wd    256
#define HEADS 8
#define Mrows 2048
#define K1    2048
#define F1    16384
#define K2    16384
#define N2    2048

#define TM 128
#define TN 128
#define BK 64                       // bf16 per chunk = 128B rows
#define STAGES 3
#define STAGE_BYTES (TM * 128 + TN * 128)      // 32768
#define SMEM_NEED (STAGES * STAGE_BYTES)       // 98304

// ---------------------------------------------------------------------------
// Device scratch
// ---------------------------------------------------------------------------
__device__ __nv_bfloat16 g_Ah[Mrows * K1], g_Al[Mrows * K1];
__device__ __nv_bfloat16 g_Wqh[(size_t)F1 * K1], g_Wql[(size_t)F1 * K1];
__device__ __nv_bfloat16 g_Wkh[(size_t)F1 * K1], g_Wkl[(size_t)F1 * K1];
__device__ __nv_bfloat16 g_Wvh[(size_t)F1 * K1], g_Wvl[(size_t)F1 * K1];
__device__ __nv_bfloat16 g_Woh[(size_t)N2 * K2], g_Wol[(size_t)N2 * K2];
__device__ float g_q[(size_t)Mrows * F1];
__device__ float g_k[(size_t)Mrows * F1];
__device__ float g_v[(size_t)Mrows * F1];
__device__ __nv_bfloat16 g_oh[(size_t)Mrows * K2], g_ol[(size_t)Mrows * K2];

// ---------------------------------------------------------------------------
// Helpers
// ---------------------------------------------------------------------------
__device__ __forceinline__ uint32_t smem_u32(const void* p) {
    uint32_t a;
    asm("{ .reg .u64 t; cvta.to.shared.u64 t, %1; cvt.u32.u64 %0, t; }" : "=r"(a) : "l"(p));
    return a;
}
__device__ __forceinline__ void cpa16(uint32_t sa, const void* g) {
    asm volatile("cp.async.ca.shared.global [%0], [%1], 16;" :: "r"(sa), "l"(g));
}
#define CP_COMMIT() asm volatile("cp.async.commit_group;")
#define CP_WAIT(n)  asm volatile("cp.async.wait_group %0;" :: "n"(n))

#define LDSM4(r0, r1, r2, r3, a)                                              \
    asm volatile("ldmatrix.sync.aligned.m8n8.x4.shared.b16 {%0,%1,%2,%3}, [%4];" \
                 : "=r"(r0), "=r"(r1), "=r"(r2), "=r"(r3) : "r"(a))

#define MMA16816(d, a0, a1, a2, a3, b0, b1)                                   \
    asm volatile("mma.sync.aligned.m16n8k16.row.col.f32.bf16.bf16.f32 "       \
                 "{%0,%1,%2,%3}, {%4,%5,%6,%7}, {%8,%9}, {%0,%1,%2,%3};"      \
                 : "+f"((d)[0]), "+f"((d)[1]), "+f"((d)[2]), "+f"((d)[3])     \
                 : "r"(a0), "r"(a1), "r"(a2), "r"(a3), "r"(b0), "r"(b1))

__device__ __forceinline__ uint32_t sw128(uint32_t off) { return off ^ ((off >> 3) & 0x70); }

// ---------------------------------------------------------------------------
// LN1 + patchify -> bf16 hi/lo A matrix
// ---------------------------------------------------------------------------
__global__ __launch_bounds__(256)
void ln1_kernel(const float* __restrict__ x, const float* __restrict__ sc,
                const float* __restrict__ bi)
{
    int lane = threadIdx.x & 31;
    int warp = threadIdx.x >> 5;
    int pix  = blockIdx.x * 8 + warp;
    float v  = x[pix * 32 + lane];
    float su = v, sq = v * v;
#pragma unroll
    for (int off = 16; off; off >>= 1) {
        su += __shfl_xor_sync(0xffffffffu, su, off);
        sq += __shfl_xor_sync(0xffffffffu, sq, off);
    }
    float mu  = su * (1.f / 32.f);
    float var = sq * (1.f / 32.f) - mu * mu;
    float y   = (v - mu) * rsqrtf(var + 1e-6f) * sc[lane] + bi[lane];
    int b = pix >> 16, h = (pix >> 8) & 255, w = pix & 255;
    int row = b * 1024 + (h >> 3) * 32 + (w >> 3);
    int idx = row * K1 + ((h & 7) * 8 + (w & 7)) * 32 + lane;
    __nv_bfloat16 hi = __float2bfloat16(y);
    g_Ah[idx] = hi;
    g_Al[idx] = __float2bfloat16(y - __bfloat162float(hi));
}

// ---------------------------------------------------------------------------
// Transpose + split-convert weights: fp32 [K,N] -> bf16 hi/lo [N,K]
// ---------------------------------------------------------------------------
__global__ __launch_bounds__(256)
void wconv_t(const float* __restrict__ W, __nv_bfloat16* __restrict__ Oh,
             __nv_bfloat16* __restrict__ Ol, int K, int N)
{
    __shared__ float t[32][33];
    int kb = blockIdx.y * 32, nb = blockIdx.x * 32;
    int tx = threadIdx.x & 31, ty = threadIdx.x >> 5;
#pragma unroll
    for (int i = 0; i < 32; i += 8)
        t[ty + i][tx] = W[(size_t)(kb + ty + i) * N + nb + tx];
    __syncthreads();
#pragma unroll
    for (int i = 0; i < 32; i += 8) {
        float v = t[tx][ty + i];
        __nv_bfloat16 h = __float2bfloat16(v);
        size_t o = (size_t)(nb + ty + i) * K + kb + tx;
        Oh[o] = h;
        Ol[o] = __float2bfloat16(v - __bfloat162float(h));
    }
}

// ---------------------------------------------------------------------------
// Split-bf16 HGEMM (mma.sync, K_eff = 3K): C = A*B^T + bias (+X residual)
//   A hi/lo [M,K] K-major; B hi/lo [N,K] K-major (pre-transposed weights)
//   Phases: (Ah,Bh), (Al,Bh), (Ah,Bl) share one accumulator.
// ---------------------------------------------------------------------------
template <int EPI>
__global__ __launch_bounds__(256, 2)
void hgemm(const __nv_bfloat16* __restrict__ Ah, const __nv_bfloat16* __restrict__ Al,
           const __nv_bfloat16* __restrict__ Bh, const __nv_bfloat16* __restrict__ Bl,
           const float* __restrict__ bias, float* __restrict__ C,
           const float* __restrict__ X, int K)
{
    extern __shared__ char smem_raw[];
    const uint32_t tiles = smem_u32(smem_raw);
    const int tid  = threadIdx.x;
    const int w    = tid >> 5;
    const int lane = tid & 31;
    const int rowBase = blockIdx.y * TM;
    const int colBase = blockIdx.x * TN;
    const int NC  = K / BK;          // chunks per phase
    const int NCT = 3 * NC;

    // ---- loader ----
    auto load_stage = [&](int ci, int s) {
        int phase = (ci >= 2 * NC) ? 2 : (ci >= NC ? 1 : 0);
        const __nv_bfloat16* pa = (phase == 1) ? Al : Ah;
        const __nv_bfloat16* pb = (phase == 2) ? Bl : Bh;
        int k0 = (ci - phase * NC) * BK;
        uint32_t ba = tiles + (uint32_t)s * STAGE_BYTES;
        uint32_t bb = ba + TM * 128;
#pragma unroll
        for (int i = 0; i < 4; i++) {
            int q   = tid + 256 * i;
            int row = q >> 3, seg = q & 7;
            uint32_t so = sw128((uint32_t)(row * 128 + seg * 16));
            cpa16(ba + so, pa + (size_t)(rowBase + row) * K + k0 + seg * 8);
            cpa16(bb + so, pb + (size_t)(colBase + row) * K + k0 + seg * 8);
        }
        CP_COMMIT();
    };

    // ---- per-warp geometry ----
    const int mw = (w >> 2) * 64;        // warp M offset (0 / 64)
    const int nw = (w & 3) * 32;         // warp N offset (0/32/64/96)
    const int lr = lane & 15;            // ldmatrix row-within-16
    const int lh = (lane >> 4) * 8;      // k half select
    const uint32_t xr = (uint32_t)(lane & 7) << 4;   // swizzle term

    float acc[4][4][4];
#pragma unroll
    for (int mi = 0; mi < 4; mi++)
#pragma unroll
        for (int nt = 0; nt < 4; nt++)
#pragma unroll
            for (int e = 0; e < 4; e++) acc[mi][nt][e] = 0.f;

    load_stage(0, 0);
    load_stage(1, 1);

    for (int c = 0; c < NCT; c++) {
        if (c + 2 < NCT) { CP_WAIT(1); } else { CP_WAIT(0); }
        __syncthreads();
        if (c + 2 < NCT) load_stage(c + 2, (c + 2) % STAGES);

        uint32_t aA = tiles + (uint32_t)(c % STAGES) * STAGE_BYTES;
        uint32_t aB = aA + TM * 128;
        uint32_t aAr[4], aBr[2];
#pragma unroll
        for (int mi = 0; mi < 4; mi++) aAr[mi] = aA + (uint32_t)(mw + mi * 16 + lr) * 128;
#pragma unroll
        for (int nj = 0; nj < 2; nj++) aBr[nj] = aB + (uint32_t)(nw + nj * 16 + lr) * 128;

#pragma unroll
        for (int kk = 0; kk < BK; kk += 16) {
            uint32_t kt = ((uint32_t)(kk + lh) * 2) ^ xr;
            uint32_t a[4][4];
#pragma unroll
            for (int mi = 0; mi < 4; mi++)
                LDSM4(a[mi][0], a[mi][1], a[mi][2], a[mi][3], aAr[mi] + kt);
            uint32_t b[4][2];
#pragma unroll
            for (int nj = 0; nj < 2; nj++) {
                uint32_t t0, t1, t2, t3;
                LDSM4(t0, t1, t2, t3, aBr[nj] + kt);
                b[nj * 2 + 0][0] = t0; b[nj * 2 + 0][1] = t2;
                b[nj * 2 + 1][0] = t1; b[nj * 2 + 1][1] = t3;
            }
#pragma unroll
            for (int mi = 0; mi < 4; mi++)
#pragma unroll
                for (int nt = 0; nt < 4; nt++)
                    MMA16816(acc[mi][nt], a[mi][0], a[mi][1], a[mi][2], a[mi][3],
                             b[nt][0], b[nt][1]);
        }
        __syncthreads();
    }

    // ---- epilogue: scatter with bias (+residual) ----
#pragma unroll
    for (int mi = 0; mi < 4; mi++) {
#pragma unroll
        for (int nt = 0; nt < 4; nt++) {
            int r0 = rowBase + mw + mi * 16 + (lane >> 2);
            int f0 = colBase + nw + nt * 8 + (lane & 3) * 2;
#pragma unroll
            for (int e = 0; e < 4; e++) {
                int r = r0 + (e >> 1) * 8;
                int f = f0 + (e & 1);
                float v = acc[mi][nt][e] + bias[f];
                int b_ = r >> 10, ghgw = r & 1023;
                if (EPI == 0) {
                    int head = f & 7, p1 = (f >> 3) & 7, p0 = (f >> 6) & 7, cc = f >> 9;
                    C[(size_t)(((b_ * 8 + head) * 1024 + ghgw) * 32 + cc) * 64 + p0 * 8 + p1] = v;
                } else {
                    int gh = ghgw >> 5, gw = ghgw & 31;
                    int p1 = f & 7, p0 = (f >> 3) & 7, cc = f >> 6;
                    size_t idx = (size_t)((b_ * 256 + gh * 8 + p0) * 256 + gw * 8 + p1) * 32 + cc;
                    C[idx] = v + X[idx];
                }
            }
        }
    }
}

// ---------------------------------------------------------------------------
// fused 8x8 circular conv + LN2 + V-gate -> bf16 hi/lo im2col
// ---------------------------------------------------------------------------
__global__ __launch_bounds__(256)
void fsas_kernel(const float* __restrict__ ln2s, const float* __restrict__ ln2b)
{
    __shared__ float sq[32][65], sk[32][65], sv[32][65], so[32][65];
    __shared__ float smu[64], srv[64];

    int tid = threadIdx.x;
    int blk = blockIdx.x;
    int bh = blk >> 10, ghgw = blk & 1023;
    int b = bh >> 3, head = bh & 7;
    size_t base = (size_t)blk * 2048;

    for (int i = tid; i < 2048; i += 256) {
        int c = i >> 6, p = i & 63;
        sq[c][p] = g_q[base + i];
        sk[c][p] = g_k[base + i];
        sv[c][p] = g_v[base + i];
    }
    __syncthreads();

    int c = tid & 31, p0 = tid >> 5;
    float out[8] = {0, 0, 0, 0, 0, 0, 0, 0};
#pragma unroll
    for (int a0 = 0; a0 < 8; a0++) {
        const float* qr = &sq[c][a0 * 8];
        const float* kr = &sk[c][((p0 - a0) & 7) * 8];
        float kv[8];
#pragma unroll
        for (int t = 0; t < 8; t++) kv[t] = kr[t];
#pragma unroll
        for (int a1 = 0; a1 < 8; a1++) {
            float qa = qr[a1];
#pragma unroll
            for (int p1 = 0; p1 < 8; p1++) out[p1] += qa * kv[(p1 - a1) & 7];
        }
    }
#pragma unroll
    for (int p1 = 0; p1 < 8; p1++) so[c][p0 * 8 + p1] = out[p1];
    __syncthreads();

    if (tid < 64) {
        float s = 0.f, s2 = 0.f;
#pragma unroll
        for (int cc = 0; cc < 32; cc++) { float v = so[cc][tid]; s += v; s2 += v * v; }
        float mu = s * (1.f / 32.f);
        float var = s2 * (1.f / 32.f) - mu * mu;
        smu[tid] = mu;
        srv[tid] = rsqrtf(var + 1e-6f);
    }
    __syncthreads();

    size_t orow = ((size_t)b * 1024 + ghgw) * K2 + head * 32;
    for (int i = tid; i < 2048; i += 256) {
        int p = i >> 5, cc = i & 31;
        float val = (so[cc][p] - smu[p]) * srv[p] * ln2s[cc] + ln2b[cc];
        val *= sv[cc][p];
        __nv_bfloat16 hi = __float2bfloat16(val);
        size_t o = orow + (size_t)p * 256 + cc;
        g_oh[o] = hi;
        g_ol[o] = __float2bfloat16(val - __bfloat162float(hi));
    }
}

// ---------------------------------------------------------------------------
// Launch
// ---------------------------------------------------------------------------
extern "C" void kernel_launch(void* const* d_in, const int* in_sizes, int n_in,
                              void* d_out, int out_size)
{
    const float* x    = (const float*)d_in[0];
    const float* ln1s = (const float*)d_in[1];
    const float* ln1b = (const float*)d_in[2];
    const float* Wq   = (const float*)d_in[3];
    const float* bq   = (const float*)d_in[4];
    const float* Wk   = (const float*)d_in[5];
    const float* bk   = (const float*)d_in[6];
    const float* Wv   = (const float*)d_in[7];
    const float* bv   = (const float*)d_in[8];
    const float* ln2s = (const float*)d_in[9];
    const float* ln2b = (const float*)d_in[10];
    const float* Wo   = (const float*)d_in[11];
    const float* bo   = (const float*)d_in[12];
    float* out = (float*)d_out;

    cudaFuncSetAttribute(hgemm<0>, cudaFuncAttributeMaxDynamicSharedMemorySize, SMEM_NEED);
    cudaFuncSetAttribute(hgemm<1>, cudaFuncAttributeMaxDynamicSharedMemorySize, SMEM_NEED);

    __nv_bfloat16 *pAh, *pAl, *pWqh, *pWql, *pWkh, *pWkl, *pWvh, *pWvl, *pWoh, *pWol, *poh, *pol;
    float *pq, *pk, *pv;
    cudaGetSymbolAddress((void**)&pAh, g_Ah);   cudaGetSymbolAddress((void**)&pAl, g_Al);
    cudaGetSymbolAddress((void**)&pWqh, g_Wqh); cudaGetSymbolAddress((void**)&pWql, g_Wql);
    cudaGetSymbolAddress((void**)&pWkh, g_Wkh); cudaGetSymbolAddress((void**)&pWkl, g_Wkl);
    cudaGetSymbolAddress((void**)&pWvh, g_Wvh); cudaGetSymbolAddress((void**)&pWvl, g_Wvl);
    cudaGetSymbolAddress((void**)&pWoh, g_Woh); cudaGetSymbolAddress((void**)&pWol, g_Wol);
    cudaGetSymbolAddress((void**)&poh, g_oh);   cudaGetSymbolAddress((void**)&pol, g_ol);
    cudaGetSymbolAddress((void**)&pq, g_q);
    cudaGetSymbolAddress((void**)&pk, g_k);
    cudaGetSymbolAddress((void**)&pv, g_v);

    // 1) LN1 + patchify (bf16 split A)
    ln1_kernel<<<(Bn * Hn * Wd) / 8, 256>>>(x, ln1s, ln1b);

    // 2) weight transpose + split-convert
    dim3 gw1(F1 / 32, K1 / 32);
    wconv_t<<<gw1, 256>>>(Wq, pWqh, pWql, K1, F1);
    wconv_t<<<gw1, 256>>>(Wk, pWkh, pWkl, K1, F1);
    wconv_t<<<gw1, 256>>>(Wv, pWvh, pWvl, K1, F1);
    dim3 gw2(N2 / 32, K2 / 32);
    wconv_t<<<gw2, 256>>>(Wo, pWoh, pWol, K2, N2);

    // 3) QKV projections on tensor cores (mma.sync)
    dim3 g1(F1 / TN, Mrows / TM);
    hgemm<0><<<g1, 256, SMEM_NEED>>>(pAh, pAl, pWqh, pWql, bq, pq, nullptr, K1);
    hgemm<0><<<g1, 256, SMEM_NEED>>>(pAh, pAl, pWkh, pWkl, bk, pk, nullptr, K1);
    hgemm<0><<<g1, 256, SMEM_NEED>>>(pAh, pAl, pWvh, pWvl, bv, pv, nullptr, K1);

    // 4) circular conv + LN2 + gate
    fsas_kernel<<<Bn * HEADS * 1024, 256>>>(ln2s, ln2b);

    // 5) output projection + bias + residual
    dim3 g2(N2 / TN, Mrows / TM);
    hgemm<1><<<g2, 256, SMEM_NEED>>>(poh, pol, pWoh, pWol, bo, out, x, K2);
}

// round 6
// speedup vs baseline: 2.9791x; 1.4760x over previous
#include <cuda_runtime.h>
#include <cuda_fp16.h>
#include <cstdint>

// ---------------------------------------------------------------------------
#define Bn    2
#define Mrows 2048
#define K1    2048
#define F1    16384
#define K2    16384
#define N2    2048

#define TM 128
#define TN 256
#define BK 64
#define SA_H 0
#define SA_L (TM * 128)
#define SB   (2 * TM * 128)
#define STAGE_B (2 * TM * 128 + TN * 128)   // 65536
#define GSMEM (3 * STAGE_B)                 // 196608

#define FS_ELEM 18464                        // 32*577 + pad coverage
#define FS_SMEM (3 * FS_ELEM * 4)            // 221568

// ---------------------------------------------------------------------------
__device__ __half g_Ah[Mrows * K1], g_Al[Mrows * K1];
__device__ __half g_Wq[(size_t)F1 * K1];
__device__ __half g_Wk[(size_t)F1 * K1];
__device__ __half g_Wv[(size_t)F1 * K1];
__device__ __half g_Wo[(size_t)N2 * K2];
__device__ float g_q[(size_t)Mrows * F1];
__device__ float g_k[(size_t)Mrows * F1];
__device__ float g_v[(size_t)Mrows * F1];
__device__ __half g_oh[(size_t)Mrows * K2], g_ol[(size_t)Mrows * K2];

// ---------------------------------------------------------------------------
__device__ __forceinline__ uint32_t smem_u32(const void* p) {
    uint32_t a;
    asm("{ .reg .u64 t; cvta.to.shared.u64 t, %1; cvt.u32.u64 %0, t; }" : "=r"(a) : "l"(p));
    return a;
}
__device__ __forceinline__ void cpa16(uint32_t sa, const void* g) {
    asm volatile("cp.async.ca.shared.global [%0], [%1], 16;" :: "r"(sa), "l"(g));
}
#define CP_COMMIT() asm volatile("cp.async.commit_group;")
#define CP_WAIT(n)  asm volatile("cp.async.wait_group %0;" :: "n"(n))

#define LDSM4(r0, r1, r2, r3, a)                                              \
    asm volatile("ldmatrix.sync.aligned.m8n8.x4.shared.b16 {%0,%1,%2,%3}, [%4];" \
                 : "=r"(r0), "=r"(r1), "=r"(r2), "=r"(r3) : "r"(a))

#define MMAH(d, a0, a1, a2, a3, b0, b1)                                       \
    asm volatile("mma.sync.aligned.m16n8k16.row.col.f32.f16.f16.f32 "         \
                 "{%0,%1,%2,%3}, {%4,%5,%6,%7}, {%8,%9}, {%0,%1,%2,%3};"      \
                 : "+f"((d)[0]), "+f"((d)[1]), "+f"((d)[2]), "+f"((d)[3])     \
                 : "r"(a0), "r"(a1), "r"(a2), "r"(a3), "r"(b0), "r"(b1))

__device__ __forceinline__ uint32_t sw128(uint32_t off) { return off ^ ((off >> 3) & 0x70); }

// ---------------------------------------------------------------------------
// LN1 + patchify -> fp16 hi/lo A [2048][2048] row-major, k = (p0*8+p1)*32+c
// ---------------------------------------------------------------------------
__global__ __launch_bounds__(256)
void ln1_kernel(const float* __restrict__ x, const float* __restrict__ sc,
                const float* __restrict__ bi)
{
    int lane = threadIdx.x & 31;
    int warp = threadIdx.x >> 5;
    int pix  = blockIdx.x * 8 + warp;
    float v  = x[pix * 32 + lane];
    float su = v, sq = v * v;
#pragma unroll
    for (int off = 16; off; off >>= 1) {
        su += __shfl_xor_sync(0xffffffffu, su, off);
        sq += __shfl_xor_sync(0xffffffffu, sq, off);
    }
    float mu  = su * (1.f / 32.f);
    float var = sq * (1.f / 32.f) - mu * mu;
    float y   = (v - mu) * rsqrtf(var + 1e-6f) * sc[lane] + bi[lane];
    int b = pix >> 16, h = (pix >> 8) & 255, w = pix & 255;
    int row = b * 1024 + (h >> 3) * 32 + (w >> 3);
    int idx = row * K1 + ((h & 7) * 8 + (w & 7)) * 32 + lane;
    __half hi = __float2half(y);
    g_Ah[idx] = hi;
    g_Al[idx] = __float2half(y - __half2float(hi));
}

// ---------------------------------------------------------------------------
// Transpose + fp16 convert: fp32 [K,N] -> fp16 [N,K]
// ---------------------------------------------------------------------------
__global__ __launch_bounds__(256)
void wconv_t(const float* __restrict__ W, __half* __restrict__ O, int K, int N)
{
    __shared__ float t[32][33];
    int kb = blockIdx.y * 32, nb = blockIdx.x * 32;
    int tx = threadIdx.x & 31, ty = threadIdx.x >> 5;
#pragma unroll
    for (int i = 0; i < 32; i += 8)
        t[ty + i][tx] = W[(size_t)(kb + ty + i) * N + nb + tx];
    __syncthreads();
#pragma unroll
    for (int i = 0; i < 32; i += 8)
        O[(size_t)(nb + ty + i) * K + kb + tx] = __float2half(t[tx][ty + i]);
}

// ---------------------------------------------------------------------------
// 2-term fp16 HGEMM: C = (Ah+Al)*Bh^T + bias
//   CTA 128x256, 8 warps of 64x64, BK=64 (128B rows, SW128), 3 stages.
//   EPI==0: C row-major [M,N] (+bias), 3 outputs selected by blockIdx.z
//   EPI==1: scatter into final [B,H,W,C] + bias + residual X
// ---------------------------------------------------------------------------
template <int EPI>
__global__ __launch_bounds__(256)
void hgemm(const __half* __restrict__ Ah, const __half* __restrict__ Al,
           const __half* __restrict__ B0, const __half* __restrict__ B1,
           const __half* __restrict__ B2,
           const float* __restrict__ bi0, const float* __restrict__ bi1,
           const float* __restrict__ bi2,
           float* __restrict__ C0, float* __restrict__ C1, float* __restrict__ C2,
           const float* __restrict__ X, int K, int N)
{
    extern __shared__ char smem_raw[];
    const uint32_t tiles = smem_u32(smem_raw);
    const int z = blockIdx.z;
    const __half* Bp  = (z == 0) ? B0 : (z == 1) ? B1 : B2;
    const float* bias = (z == 0) ? bi0 : (z == 1) ? bi1 : bi2;
    float* C          = (z == 0) ? C0 : (z == 1) ? C1 : C2;

    const int tid  = threadIdx.x;
    const int w    = tid >> 5;
    const int lane = tid & 31;
    const int rowBase = blockIdx.y * TM;
    const int colBase = blockIdx.x * TN;
    const int NC = K / BK;

    auto load_stage = [&](int c, int s) {
        uint32_t base = tiles + (uint32_t)s * STAGE_B;
        int k0 = c * BK;
#pragma unroll
        for (int i = 0; i < 4; i++) {
            int q = tid + 256 * i;
            int row = q >> 3, seg = q & 7;
            uint32_t so = sw128((uint32_t)(row * 128 + seg * 16));
            size_t go = (size_t)(rowBase + row) * K + k0 + seg * 8;
            cpa16(base + SA_H + so, Ah + go);
            cpa16(base + SA_L + so, Al + go);
        }
#pragma unroll
        for (int i = 0; i < 8; i++) {
            int q = tid + 256 * i;
            int row = q >> 3, seg = q & 7;
            uint32_t so = sw128((uint32_t)(row * 128 + seg * 16));
            cpa16(base + SB + so, Bp + (size_t)(colBase + row) * K + k0 + seg * 8);
        }
        CP_COMMIT();
    };

    const int mw = (w >> 2) * 64;
    const int nw = (w & 3) * 64;
    const int lr = lane & 15;
    const int lh = (lane >> 4) * 8;
    const uint32_t xr = (uint32_t)(lane & 7) << 4;

    float acc[4][8][4];
#pragma unroll
    for (int mi = 0; mi < 4; mi++)
#pragma unroll
        for (int nt = 0; nt < 8; nt++)
#pragma unroll
            for (int e = 0; e < 4; e++) acc[mi][nt][e] = 0.f;

    load_stage(0, 0);
    load_stage(1, 1);

    for (int c = 0; c < NC; c++) {
        if (c + 2 < NC) { CP_WAIT(1); } else { CP_WAIT(0); }
        __syncthreads();
        if (c + 2 < NC) load_stage(c + 2, (c + 2) % 3);

        uint32_t sbase = tiles + (uint32_t)(c % 3) * STAGE_B;
        uint32_t aH[4], aL[4], aBr[4];
#pragma unroll
        for (int mi = 0; mi < 4; mi++) {
            aH[mi] = sbase + SA_H + (uint32_t)(mw + mi * 16 + lr) * 128;
            aL[mi] = sbase + SA_L + (uint32_t)(mw + mi * 16 + lr) * 128;
        }
#pragma unroll
        for (int nj = 0; nj < 4; nj++)
            aBr[nj] = sbase + SB + (uint32_t)(nw + nj * 16 + lr) * 128;

#pragma unroll
        for (int kk = 0; kk < BK; kk += 16) {
            uint32_t kt = ((uint32_t)(kk + lh) * 2) ^ xr;
            uint32_t b[8][2];
#pragma unroll
            for (int nj = 0; nj < 4; nj++) {
                uint32_t t0, t1, t2, t3;
                LDSM4(t0, t1, t2, t3, aBr[nj] + kt);
                b[nj * 2 + 0][0] = t0; b[nj * 2 + 0][1] = t2;
                b[nj * 2 + 1][0] = t1; b[nj * 2 + 1][1] = t3;
            }
            uint32_t a[4][4];
#pragma unroll
            for (int mi = 0; mi < 4; mi++)
                LDSM4(a[mi][0], a[mi][1], a[mi][2], a[mi][3], aH[mi] + kt);
#pragma unroll
            for (int mi = 0; mi < 4; mi++)
#pragma unroll
                for (int nt = 0; nt < 8; nt++)
                    MMAH(acc[mi][nt], a[mi][0], a[mi][1], a[mi][2], a[mi][3],
                         b[nt][0], b[nt][1]);
#pragma unroll
            for (int mi = 0; mi < 4; mi++)
                LDSM4(a[mi][0], a[mi][1], a[mi][2], a[mi][3], aL[mi] + kt);
#pragma unroll
            for (int mi = 0; mi < 4; mi++)
#pragma unroll
                for (int nt = 0; nt < 8; nt++)
                    MMAH(acc[mi][nt], a[mi][0], a[mi][1], a[mi][2], a[mi][3],
                         b[nt][0], b[nt][1]);
        }
        __syncthreads();
    }

    // epilogue
#pragma unroll
    for (int mi = 0; mi < 4; mi++) {
#pragma unroll
        for (int nt = 0; nt < 8; nt++) {
            int r0 = rowBase + mw + mi * 16 + (lane >> 2);
            int f  = colBase + nw + nt * 8 + (lane & 3) * 2;
            float b0 = bias[f], b1 = bias[f + 1];
            if (EPI == 0) {
                C[(size_t)r0 * N + f]           = acc[mi][nt][0] + b0;
                C[(size_t)r0 * N + f + 1]       = acc[mi][nt][1] + b1;
                C[(size_t)(r0 + 8) * N + f]     = acc[mi][nt][2] + b0;
                C[(size_t)(r0 + 8) * N + f + 1] = acc[mi][nt][3] + b1;
            } else {
#pragma unroll
                for (int e = 0; e < 4; e++) {
                    int r = r0 + (e >> 1) * 8;
                    int ff = f + (e & 1);
                    float v = acc[mi][nt][e] + ((e & 1) ? b1 : b0);
                    int b_ = r >> 10, ghgw = r & 1023;
                    int gh = ghgw >> 5, gw = ghgw & 31;
                    int p1 = ff & 7, p0 = (ff >> 3) & 7, cc = ff >> 6;
                    size_t idx = (size_t)((b_ * 256 + gh * 8 + p0) * 256 + gw * 8 + p1) * 32 + cc;
                    C[idx] = v + X[idx];
                }
            }
        }
    }
}

// ---------------------------------------------------------------------------
// fsas v2: one CTA per patch-row r (all 8 heads).
//   reads g_q/g_k/g_v row-major [r][f], f = c*512 + p0*64 + p1*8 + head
//   8x8 circular conv + LN2(c) + V-gate -> fp16 hi/lo [r][p*256+head*32+c]
// smem layout per tensor: [c][p][head] flat idx = c*577 + p*9 + head
// ---------------------------------------------------------------------------
__global__ __launch_bounds__(256)
void fsas2(const float* __restrict__ ln2s, const float* __restrict__ ln2b)
{
    extern __shared__ float fs[];
    float* fq = fs;
    float* fk = fs + FS_ELEM;
    float* fv = fs + 2 * FS_ELEM;
    int tid = threadIdx.x;
    int r = blockIdx.x;
    size_t rb = (size_t)r * 16384;

    for (int i = tid; i < 16384; i += 256) {
        int head = i & 7, p = (i >> 3) & 63, c = i >> 9;
        int s = c * 577 + p * 9 + head;
        fq[s] = g_q[rb + i];
        fk[s] = g_k[rb + i];
        fv[s] = g_v[rb + i];
    }
    __syncthreads();

    int head = tid >> 5, c = tid & 31;
    const float* q0 = fq + c * 577 + head;
    const float* k0 = fk + c * 577 + head;
    float out[64];
#pragma unroll
    for (int p = 0; p < 64; p++) out[p] = 0.f;

#pragma unroll
    for (int a0 = 0; a0 < 8; a0++) {
        float qv[8];
#pragma unroll
        for (int a1 = 0; a1 < 8; a1++) qv[a1] = q0[(a0 * 8 + a1) * 9];
#pragma unroll
        for (int p0 = 0; p0 < 8; p0++) {
            int kr = (p0 - a0) & 7;
            float kv[8];
#pragma unroll
            for (int t = 0; t < 8; t++) kv[t] = k0[(kr * 8 + t) * 9];
#pragma unroll
            for (int a1 = 0; a1 < 8; a1++) {
                float qa = qv[a1];
#pragma unroll
                for (int p1 = 0; p1 < 8; p1++)
                    out[p0 * 8 + p1] += qa * kv[(p1 - a1) & 7];
            }
        }
    }
    __syncthreads();     // conv everywhere done; fq region reusable

    float sc = ln2s[c], sb = ln2b[c];
    __half* sgh = (__half*)fq;
    __half* sgl = sgh + 64 * 264;
    const float* v0 = fv + c * 577 + head;

#pragma unroll
    for (int p = 0; p < 64; p++) {
        float s = out[p], s2 = out[p] * out[p];
#pragma unroll
        for (int o = 16; o; o >>= 1) {
            s  += __shfl_xor_sync(0xffffffffu, s,  o);
            s2 += __shfl_xor_sync(0xffffffffu, s2, o);
        }
        float mu  = s * (1.f / 32.f);
        float var = s2 * (1.f / 32.f) - mu * mu;
        float val = (out[p] - mu) * rsqrtf(var + 1e-6f) * sc + sb;
        val *= v0[p * 9];
        __half hi = __float2half(val);
        __half lo = __float2half(val - __half2float(hi));
        sgh[p * 264 + head * 32 + c] = hi;
        sgl[p * 264 + head * 32 + c] = lo;
    }
    __syncthreads();

    uint32_t* gh = (uint32_t*)g_oh;
    uint32_t* gl = (uint32_t*)g_ol;
    size_t rb2 = (size_t)r * 8192;
    for (int i = tid; i < 8192; i += 256) {
        int p = i >> 7, cl = i & 127;
        gh[rb2 + i] = *(uint32_t*)&sgh[p * 264 + cl * 2];
        gl[rb2 + i] = *(uint32_t*)&sgl[p * 264 + cl * 2];
    }
}

// ---------------------------------------------------------------------------
extern "C" void kernel_launch(void* const* d_in, const int* in_sizes, int n_in,
                              void* d_out, int out_size)
{
    const float* x    = (const float*)d_in[0];
    const float* ln1s = (const float*)d_in[1];
    const float* ln1b = (const float*)d_in[2];
    const float* Wq   = (const float*)d_in[3];
    const float* bq   = (const float*)d_in[4];
    const float* Wk   = (const float*)d_in[5];
    const float* bk   = (const float*)d_in[6];
    const float* Wv   = (const float*)d_in[7];
    const float* bv   = (const float*)d_in[8];
    const float* ln2s = (const float*)d_in[9];
    const float* ln2b = (const float*)d_in[10];
    const float* Wo   = (const float*)d_in[11];
    const float* bo   = (const float*)d_in[12];
    float* out = (float*)d_out;

    cudaFuncSetAttribute(hgemm<0>, cudaFuncAttributeMaxDynamicSharedMemorySize, GSMEM);
    cudaFuncSetAttribute(hgemm<1>, cudaFuncAttributeMaxDynamicSharedMemorySize, GSMEM);
    cudaFuncSetAttribute(fsas2,    cudaFuncAttributeMaxDynamicSharedMemorySize, FS_SMEM);

    __half *pAh, *pAl, *pWq, *pWk, *pWv, *pWo, *poh, *pol;
    float *pq, *pk, *pv;
    cudaGetSymbolAddress((void**)&pAh, g_Ah); cudaGetSymbolAddress((void**)&pAl, g_Al);
    cudaGetSymbolAddress((void**)&pWq, g_Wq); cudaGetSymbolAddress((void**)&pWk, g_Wk);
    cudaGetSymbolAddress((void**)&pWv, g_Wv); cudaGetSymbolAddress((void**)&pWo, g_Wo);
    cudaGetSymbolAddress((void**)&poh, g_oh); cudaGetSymbolAddress((void**)&pol, g_ol);
    cudaGetSymbolAddress((void**)&pq, g_q);
    cudaGetSymbolAddress((void**)&pk, g_k);
    cudaGetSymbolAddress((void**)&pv, g_v);

    // 1) LN1 + patchify
    ln1_kernel<<<(Bn * 256 * 256) / 8, 256>>>(x, ln1s, ln1b);

    // 2) weight transpose + fp16 convert
    dim3 gw1(F1 / 32, K1 / 32);
    wconv_t<<<gw1, 256>>>(Wq, pWq, K1, F1);
    wconv_t<<<gw1, 256>>>(Wk, pWk, K1, F1);
    wconv_t<<<gw1, 256>>>(Wv, pWv, K1, F1);
    dim3 gw2(N2 / 32, K2 / 32);
    wconv_t<<<gw2, 256>>>(Wo, pWo, K2, N2);

    // 3) QKV projections (merged, z selects matrix), row-major outputs
    dim3 g1(F1 / TN, Mrows / TM, 3);
    hgemm<0><<<g1, 256, GSMEM>>>(pAh, pAl, pWq, pWk, pWv, bq, bk, bv,
                                 pq, pk, pv, nullptr, K1, F1);

    // 4) circular conv + LN2 + gate -> fp16 hi/lo im2col
    fsas2<<<Mrows, 256, FS_SMEM>>>(ln2s, ln2b);

    // 5) output projection + bias + residual
    dim3 g2(N2 / TN, Mrows / TM, 1);
    hgemm<1><<<g2, 256, GSMEM>>>(poh, pol, pWo, pWo, pWo, bo, bo, bo,
                                 out, out, out, x, K2, N2);
}

// round 7
// speedup vs baseline: 3.0611x; 1.0275x over previous
#include <cuda_runtime.h>
#include <cuda_fp16.h>
#include <cstdint>

// ---------------------------------------------------------------------------
#define Bn    2
#define Mrows 2048
#define K1    2048
#define F1    16384
#define K2    16384
#define N2    2048

#define TM 128
#define TN 256
#define BK 64
#define SA_H 0
#define SA_L (TM * 128)
#define SB   (2 * TM * 128)
#define STAGE_B (2 * TM * 128 + TN * 128)   // 65536
#define GSMEM (3 * STAGE_B)                 // 196608

#define FS_ELEM 18464
#define FS_SMEM (3 * FS_ELEM * 4)            // 221568

// ---------------------------------------------------------------------------
__device__ __half g_Ah[Mrows * K1], g_Al[Mrows * K1];
__device__ __half g_Wq[(size_t)F1 * K1];
__device__ __half g_Wk[(size_t)F1 * K1];
__device__ __half g_Wv[(size_t)F1 * K1];
__device__ __half g_Wo[(size_t)N2 * K2];
__device__ float g_q[(size_t)Mrows * F1];
__device__ float g_k[(size_t)Mrows * F1];
__device__ float g_v[(size_t)Mrows * F1];
__device__ __half g_oh[(size_t)Mrows * K2], g_ol[(size_t)Mrows * K2];

// ---------------------------------------------------------------------------
__device__ __forceinline__ uint32_t smem_u32(const void* p) {
    uint32_t a;
    asm("{ .reg .u64 t; cvta.to.shared.u64 t, %1; cvt.u32.u64 %0, t; }" : "=r"(a) : "l"(p));
    return a;
}
__device__ __forceinline__ void cpa16(uint32_t sa, const void* g) {
    asm volatile("cp.async.ca.shared.global [%0], [%1], 16;" :: "r"(sa), "l"(g));
}
#define CP_COMMIT() asm volatile("cp.async.commit_group;")
#define CP_WAIT(n)  asm volatile("cp.async.wait_group %0;" :: "n"(n))

#define LDSM4(r0, r1, r2, r3, a)                                              \
    asm volatile("ldmatrix.sync.aligned.m8n8.x4.shared.b16 {%0,%1,%2,%3}, [%4];" \
                 : "=r"(r0), "=r"(r1), "=r"(r2), "=r"(r3) : "r"(a))

#define MMAH(d, a0, a1, a2, a3, b0, b1)                                       \
    asm volatile("mma.sync.aligned.m16n8k16.row.col.f32.f16.f16.f32 "         \
                 "{%0,%1,%2,%3}, {%4,%5,%6,%7}, {%8,%9}, {%0,%1,%2,%3};"      \
                 : "+f"((d)[0]), "+f"((d)[1]), "+f"((d)[2]), "+f"((d)[3])     \
                 : "r"(a0), "r"(a1), "r"(a2), "r"(a3), "r"(b0), "r"(b1))

__device__ __forceinline__ uint32_t sw128(uint32_t off) { return off ^ ((off >> 3) & 0x70); }

// ---------------------------------------------------------------------------
// LN1 + patchify -> fp16 hi/lo A [2048][2048] row-major, k = (p0*8+p1)*32+c
// ---------------------------------------------------------------------------
__global__ __launch_bounds__(256)
void ln1_kernel(const float* __restrict__ x, const float* __restrict__ sc,
                const float* __restrict__ bi)
{
    int lane = threadIdx.x & 31;
    int warp = threadIdx.x >> 5;
    int pix  = blockIdx.x * 8 + warp;
    float v  = x[pix * 32 + lane];
    float su = v, sq = v * v;
#pragma unroll
    for (int off = 16; off; off >>= 1) {
        su += __shfl_xor_sync(0xffffffffu, su, off);
        sq += __shfl_xor_sync(0xffffffffu, sq, off);
    }
    float mu  = su * (1.f / 32.f);
    float var = sq * (1.f / 32.f) - mu * mu;
    float y   = (v - mu) * rsqrtf(var + 1e-6f) * sc[lane] + bi[lane];
    int b = pix >> 16, h = (pix >> 8) & 255, w = pix & 255;
    int row = b * 1024 + (h >> 3) * 32 + (w >> 3);
    int idx = row * K1 + ((h & 7) * 8 + (w & 7)) * 32 + lane;
    __half hi = __float2half(y);
    g_Ah[idx] = hi;
    g_Al[idx] = __float2half(y - __half2float(hi));
}

// ---------------------------------------------------------------------------
// Transpose + fp16 convert: fp32 [K,N] -> fp16 [N,K]; z selects matrix.
// Tile 64(K) x 32(N); half2 writes, 128B coalesced along K.
// ---------------------------------------------------------------------------
__global__ __launch_bounds__(256)
void wconv_t(const float* __restrict__ W0, const float* __restrict__ W1,
             const float* __restrict__ W2,
             __half* __restrict__ O0, __half* __restrict__ O1, __half* __restrict__ O2,
             int K, int N)
{
    const int z = blockIdx.z;
    const float* W = (z == 0) ? W0 : (z == 1) ? W1 : W2;
    __half* O      = (z == 0) ? O0 : (z == 1) ? O1 : O2;

    __shared__ float t[64][33];
    int kb = blockIdx.y * 64, nb = blockIdx.x * 32;
    int tx = threadIdx.x & 31, ty = threadIdx.x >> 5;   // ty 0..7
#pragma unroll
    for (int i = 0; i < 8; i++)
        t[ty + 8 * i][tx] = W[(size_t)(kb + ty + 8 * i) * N + nb + tx];
    __syncthreads();
#pragma unroll
    for (int i = 0; i < 4; i++) {
        int n = ty * 4 + i;
        __half2 h = __floats2half2_rn(t[tx * 2][n], t[tx * 2 + 1][n]);
        *(__half2*)&O[(size_t)(nb + n) * K + kb + tx * 2] = h;
    }
}

// ---------------------------------------------------------------------------
// 2-term fp16 HGEMM with register double-buffering of B/Ah LDSM:
//   C = (Ah+Al)*B^T + bias.  CTA 128x256, 8 warps of 64x64, BK=64, 3 stages.
//   EPI==0: C row-major [M,N] (+bias), z selects {q,k,v}
//   EPI==1: scatter into final [B,H,W,C] + bias + residual X
// ---------------------------------------------------------------------------
template <int EPI>
__global__ __launch_bounds__(256, 1)
void hgemm(const __half* __restrict__ Ah, const __half* __restrict__ Al,
           const __half* __restrict__ B0, const __half* __restrict__ B1,
           const __half* __restrict__ B2,
           const float* __restrict__ bi0, const float* __restrict__ bi1,
           const float* __restrict__ bi2,
           float* __restrict__ C0, float* __restrict__ C1, float* __restrict__ C2,
           const float* __restrict__ X, int K, int N)
{
    extern __shared__ char smem_raw[];
    const uint32_t tiles = smem_u32(smem_raw);
    const int z = blockIdx.z;
    const __half* Bp  = (z == 0) ? B0 : (z == 1) ? B1 : B2;
    const float* bias = (z == 0) ? bi0 : (z == 1) ? bi1 : bi2;
    float* C          = (z == 0) ? C0 : (z == 1) ? C1 : C2;

    const int tid  = threadIdx.x;
    const int w    = tid >> 5;
    const int lane = tid & 31;
    const int rowBase = blockIdx.y * TM;
    const int colBase = blockIdx.x * TN;
    const int NC = K / BK;

    auto load_stage = [&](int c, int s) {
        uint32_t base = tiles + (uint32_t)s * STAGE_B;
        int k0 = c * BK;
#pragma unroll
        for (int i = 0; i < 4; i++) {
            int q = tid + 256 * i;
            int row = q >> 3, seg = q & 7;
            uint32_t so = sw128((uint32_t)(row * 128 + seg * 16));
            size_t go = (size_t)(rowBase + row) * K + k0 + seg * 8;
            cpa16(base + SA_H + so, Ah + go);
            cpa16(base + SA_L + so, Al + go);
        }
#pragma unroll
        for (int i = 0; i < 8; i++) {
            int q = tid + 256 * i;
            int row = q >> 3, seg = q & 7;
            uint32_t so = sw128((uint32_t)(row * 128 + seg * 16));
            cpa16(base + SB + so, Bp + (size_t)(colBase + row) * K + k0 + seg * 8);
        }
        CP_COMMIT();
    };

    const int mw = (w >> 2) * 64;
    const int nw = (w & 3) * 64;
    const int lr = lane & 15;
    const int lh = (lane >> 4) * 8;
    const uint32_t xr = (uint32_t)(lane & 7) << 4;

    float acc[4][8][4];
#pragma unroll
    for (int mi = 0; mi < 4; mi++)
#pragma unroll
        for (int nt = 0; nt < 8; nt++)
#pragma unroll
            for (int e = 0; e < 4; e++) acc[mi][nt][e] = 0.f;

    load_stage(0, 0);
    load_stage(1, 1);

    uint32_t bb[2][8][2], ah[2][4][4], al[4][4];

    for (int c = 0; c < NC; c++) {
        if (c + 2 < NC) { CP_WAIT(1); } else { CP_WAIT(0); }
        __syncthreads();
        if (c + 2 < NC) load_stage(c + 2, (c + 2) % 3);

        uint32_t sbase = tiles + (uint32_t)(c % 3) * STAGE_B;
        uint32_t aH[4], aL[4], aBr[4];
#pragma unroll
        for (int mi = 0; mi < 4; mi++) {
            aH[mi] = sbase + SA_H + (uint32_t)(mw + mi * 16 + lr) * 128;
            aL[mi] = sbase + SA_L + (uint32_t)(mw + mi * 16 + lr) * 128;
        }
#pragma unroll
        for (int nj = 0; nj < 4; nj++)
            aBr[nj] = sbase + SB + (uint32_t)(nw + nj * 16 + lr) * 128;

        // preload k16 step 0 (B + A-hi)
        {
            uint32_t kt = ((uint32_t)lh * 2) ^ xr;
#pragma unroll
            for (int nj = 0; nj < 4; nj++) {
                uint32_t t0, t1, t2, t3;
                LDSM4(t0, t1, t2, t3, aBr[nj] + kt);
                bb[0][nj * 2 + 0][0] = t0; bb[0][nj * 2 + 0][1] = t2;
                bb[0][nj * 2 + 1][0] = t1; bb[0][nj * 2 + 1][1] = t3;
            }
#pragma unroll
            for (int mi = 0; mi < 4; mi++)
                LDSM4(ah[0][mi][0], ah[0][mi][1], ah[0][mi][2], ah[0][mi][3],
                      aH[mi] + kt);
        }

#pragma unroll
        for (int kk = 0; kk < 4; kk++) {
            const int cur = kk & 1, nxt = cur ^ 1;
            uint32_t kt = ((uint32_t)(kk * 16 + lh) * 2) ^ xr;
            // A-lo for current step
#pragma unroll
            for (int mi = 0; mi < 4; mi++)
                LDSM4(al[mi][0], al[mi][1], al[mi][2], al[mi][3], aL[mi] + kt);
            // prefetch next step's B + A-hi while MMAs below execute
            if (kk < 3) {
                uint32_t kt2 = ((uint32_t)((kk + 1) * 16 + lh) * 2) ^ xr;
#pragma unroll
                for (int nj = 0; nj < 4; nj++) {
                    uint32_t t0, t1, t2, t3;
                    LDSM4(t0, t1, t2, t3, aBr[nj] + kt2);
                    bb[nxt][nj * 2 + 0][0] = t0; bb[nxt][nj * 2 + 0][1] = t2;
                    bb[nxt][nj * 2 + 1][0] = t1; bb[nxt][nj * 2 + 1][1] = t3;
                }
#pragma unroll
                for (int mi = 0; mi < 4; mi++)
                    LDSM4(ah[nxt][mi][0], ah[nxt][mi][1], ah[nxt][mi][2],
                          ah[nxt][mi][3], aH[mi] + kt2);
            }
#pragma unroll
            for (int mi = 0; mi < 4; mi++)
#pragma unroll
                for (int nt = 0; nt < 8; nt++)
                    MMAH(acc[mi][nt], ah[cur][mi][0], ah[cur][mi][1],
                         ah[cur][mi][2], ah[cur][mi][3], bb[cur][nt][0], bb[cur][nt][1]);
#pragma unroll
            for (int mi = 0; mi < 4; mi++)
#pragma unroll
                for (int nt = 0; nt < 8; nt++)
                    MMAH(acc[mi][nt], al[mi][0], al[mi][1], al[mi][2], al[mi][3],
                         bb[cur][nt][0], bb[cur][nt][1]);
        }
        // no trailing sync: next iteration's top __syncthreads protects reuse
    }

    // epilogue
#pragma unroll
    for (int mi = 0; mi < 4; mi++) {
#pragma unroll
        for (int nt = 0; nt < 8; nt++) {
            int r0 = rowBase + mw + mi * 16 + (lane >> 2);
            int f  = colBase + nw + nt * 8 + (lane & 3) * 2;
            float b0 = bias[f], b1 = bias[f + 1];
            if (EPI == 0) {
                C[(size_t)r0 * N + f]           = acc[mi][nt][0] + b0;
                C[(size_t)r0 * N + f + 1]       = acc[mi][nt][1] + b1;
                C[(size_t)(r0 + 8) * N + f]     = acc[mi][nt][2] + b0;
                C[(size_t)(r0 + 8) * N + f + 1] = acc[mi][nt][3] + b1;
            } else {
#pragma unroll
                for (int e = 0; e < 4; e++) {
                    int r = r0 + (e >> 1) * 8;
                    int ff = f + (e & 1);
                    float v = acc[mi][nt][e] + ((e & 1) ? b1 : b0);
                    int b_ = r >> 10, ghgw = r & 1023;
                    int gh = ghgw >> 5, gw = ghgw & 31;
                    int p1 = ff & 7, p0 = (ff >> 3) & 7, cc = ff >> 6;
                    size_t idx = (size_t)((b_ * 256 + gh * 8 + p0) * 256 + gw * 8 + p1) * 32 + cc;
                    C[idx] = v + X[idx];
                }
            }
        }
    }
}

// ---------------------------------------------------------------------------
// fsas v2: one CTA per patch-row r (all 8 heads).
//   reads g_q/g_k/g_v row-major [r][f], f = c*512 + p0*64 + p1*8 + head
//   8x8 circular conv + LN2(c) + V-gate -> fp16 hi/lo [r][p*256+head*32+c]
// ---------------------------------------------------------------------------
__global__ __launch_bounds__(256)
void fsas2(const float* __restrict__ ln2s, const float* __restrict__ ln2b)
{
    extern __shared__ float fs[];
    float* fq = fs;
    float* fk = fs + FS_ELEM;
    float* fv = fs + 2 * FS_ELEM;
    int tid = threadIdx.x;
    int r = blockIdx.x;
    size_t rb = (size_t)r * 16384;

    for (int i = tid; i < 16384; i += 256) {
        int head = i & 7, p = (i >> 3) & 63, c = i >> 9;
        int s = c * 577 + p * 9 + head;
        fq[s] = g_q[rb + i];
        fk[s] = g_k[rb + i];
        fv[s] = g_v[rb + i];
    }
    __syncthreads();

    int head = tid >> 5, c = tid & 31;
    const float* q0 = fq + c * 577 + head;
    const float* k0 = fk + c * 577 + head;
    float out[64];
#pragma unroll
    for (int p = 0; p < 64; p++) out[p] = 0.f;

#pragma unroll
    for (int a0 = 0; a0 < 8; a0++) {
        float qv[8];
#pragma unroll
        for (int a1 = 0; a1 < 8; a1++) qv[a1] = q0[(a0 * 8 + a1) * 9];
#pragma unroll
        for (int p0 = 0; p0 < 8; p0++) {
            int kr = (p0 - a0) & 7;
            float kv[8];
#pragma unroll
            for (int t = 0; t < 8; t++) kv[t] = k0[(kr * 8 + t) * 9];
#pragma unroll
            for (int a1 = 0; a1 < 8; a1++) {
                float qa = qv[a1];
#pragma unroll
                for (int p1 = 0; p1 < 8; p1++)
                    out[p0 * 8 + p1] += qa * kv[(p1 - a1) & 7];
            }
        }
    }
    __syncthreads();

    float sc = ln2s[c], sb = ln2b[c];
    __half* sgh = (__half*)fq;
    __half* sgl = sgh + 64 * 264;
    const float* v0 = fv + c * 577 + head;

#pragma unroll
    for (int p = 0; p < 64; p++) {
        float s = out[p], s2 = out[p] * out[p];
#pragma unroll
        for (int o = 16; o; o >>= 1) {
            s  += __shfl_xor_sync(0xffffffffu, s,  o);
            s2 += __shfl_xor_sync(0xffffffffu, s2, o);
        }
        float mu  = s * (1.f / 32.f);
        float var = s2 * (1.f / 32.f) - mu * mu;
        float val = (out[p] - mu) * rsqrtf(var + 1e-6f) * sc + sb;
        val *= v0[p * 9];
        __half hi = __float2half(val);
        __half lo = __float2half(val - __half2float(hi));
        sgh[p * 264 + head * 32 + c] = hi;
        sgl[p * 264 + head * 32 + c] = lo;
    }
    __syncthreads();

    uint32_t* gh = (uint32_t*)g_oh;
    uint32_t* gl = (uint32_t*)g_ol;
    size_t rb2 = (size_t)r * 8192;
    for (int i = tid; i < 8192; i += 256) {
        int p = i >> 7, cl = i & 127;
        gh[rb2 + i] = *(uint32_t*)&sgh[p * 264 + cl * 2];
        gl[rb2 + i] = *(uint32_t*)&sgl[p * 264 + cl * 2];
    }
}

// ---------------------------------------------------------------------------
extern "C" void kernel_launch(void* const* d_in, const int* in_sizes, int n_in,
                              void* d_out, int out_size)
{
    const float* x    = (const float*)d_in[0];
    const float* ln1s = (const float*)d_in[1];
    const float* ln1b = (const float*)d_in[2];
    const float* Wq   = (const float*)d_in[3];
    const float* bq   = (const float*)d_in[4];
    const float* Wk   = (const float*)d_in[5];
    const float* bk   = (const float*)d_in[6];
    const float* Wv   = (const float*)d_in[7];
    const float* bv   = (const float*)d_in[8];
    const float* ln2s = (const float*)d_in[9];
    const float* ln2b = (const float*)d_in[10];
    const float* Wo   = (const float*)d_in[11];
    const float* bo   = (const float*)d_in[12];
    float* out = (float*)d_out;

    cudaFuncSetAttribute(hgemm<0>, cudaFuncAttributeMaxDynamicSharedMemorySize, GSMEM);
    cudaFuncSetAttribute(hgemm<1>, cudaFuncAttributeMaxDynamicSharedMemorySize, GSMEM);
    cudaFuncSetAttribute(fsas2,    cudaFuncAttributeMaxDynamicSharedMemorySize, FS_SMEM);

    __half *pAh, *pAl, *pWq, *pWk, *pWv, *pWo, *poh, *pol;
    float *pq, *pk, *pv;
    cudaGetSymbolAddress((void**)&pAh, g_Ah); cudaGetSymbolAddress((void**)&pAl, g_Al);
    cudaGetSymbolAddress((void**)&pWq, g_Wq); cudaGetSymbolAddress((void**)&pWk, g_Wk);
    cudaGetSymbolAddress((void**)&pWv, g_Wv); cudaGetSymbolAddress((void**)&pWo, g_Wo);
    cudaGetSymbolAddress((void**)&poh, g_oh); cudaGetSymbolAddress((void**)&pol, g_ol);
    cudaGetSymbolAddress((void**)&pq, g_q);
    cudaGetSymbolAddress((void**)&pk, g_k);
    cudaGetSymbolAddress((void**)&pv, g_v);

    // 1) LN1 + patchify
    ln1_kernel<<<(Bn * 256 * 256) / 8, 256>>>(x, ln1s, ln1b);

    // 2) weight transpose + fp16 convert (QKV merged via z, then Wo)
    dim3 gwq(F1 / 32, K1 / 64, 3);
    wconv_t<<<gwq, 256>>>(Wq, Wk, Wv, pWq, pWk, pWv, K1, F1);
    dim3 gwo(N2 / 32, K2 / 64, 1);
    wconv_t<<<gwo, 256>>>(Wo, Wo, Wo, pWo, pWo, pWo, K2, N2);

    // 3) QKV projections (merged, z selects matrix), row-major outputs
    dim3 g1(F1 / TN, Mrows / TM, 3);
    hgemm<0><<<g1, 256, GSMEM>>>(pAh, pAl, pWq, pWk, pWv, bq, bk, bv,
                                 pq, pk, pv, nullptr, K1, F1);

    // 4) circular conv + LN2 + gate -> fp16 hi/lo im2col
    fsas2<<<Mrows, 256, FS_SMEM>>>(ln2s, ln2b);

    // 5) output projection + bias + residual
    dim3 g2(N2 / TN, Mrows / TM, 1);
    hgemm<1><<<g2, 256, GSMEM>>>(poh, pol, pWo, pWo, pWo, bo, bo, bo,
                                 out, out, out, x, K2, N2);
}

// round 8
// speedup vs baseline: 3.1969x; 1.0444x over previous
#include <cuda_runtime.h>
#include <cuda_fp16.h>
#include <cstdint>

// ---------------------------------------------------------------------------
#define Bn    2
#define Mrows 2048
#define K1    2048
#define F1    16384
#define K2    16384
#define N2    2048

#define TM 128
#define TN 256
#define BK 64
#define SA_H 0
#define SA_L (TM * 128)
#define SB   (2 * TM * 128)
#define STAGE_B (2 * TM * 128 + TN * 128)   // 65536
#define GSMEM (3 * STAGE_B)                 // 196608

#define FS_ELEM 18464
#define FS_SMEM (3 * FS_ELEM * 4)            // 221568

// ---------------------------------------------------------------------------
__device__ __half g_Ah[Mrows * K1], g_Al[Mrows * K1];
__device__ __half g_Wq[(size_t)F1 * K1];
__device__ __half g_Wk[(size_t)F1 * K1];
__device__ __half g_Wv[(size_t)F1 * K1];
__device__ __half g_Wo[(size_t)N2 * K2];
__device__ float g_q[(size_t)Mrows * F1];
__device__ float g_k[(size_t)Mrows * F1];
__device__ float g_v[(size_t)Mrows * F1];
__device__ __half g_oh[(size_t)Mrows * K2], g_ol[(size_t)Mrows * K2];

// ---------------------------------------------------------------------------
__device__ __forceinline__ uint32_t smem_u32(const void* p) {
    uint32_t a;
    asm("{ .reg .u64 t; cvta.to.shared.u64 t, %1; cvt.u32.u64 %0, t; }" : "=r"(a) : "l"(p));
    return a;
}
__device__ __forceinline__ void cpa16(uint32_t sa, const void* g) {
    asm volatile("cp.async.ca.shared.global [%0], [%1], 16;" :: "r"(sa), "l"(g));
}
#define CP_COMMIT() asm volatile("cp.async.commit_group;")
#define CP_WAIT(n)  asm volatile("cp.async.wait_group %0;" :: "n"(n))

#define LDSM4(r0, r1, r2, r3, a)                                              \
    asm volatile("ldmatrix.sync.aligned.m8n8.x4.shared.b16 {%0,%1,%2,%3}, [%4];" \
                 : "=r"(r0), "=r"(r1), "=r"(r2), "=r"(r3) : "r"(a))

#define MMAH(d, a0, a1, a2, a3, b0, b1)                                       \
    asm volatile("mma.sync.aligned.m16n8k16.row.col.f32.f16.f16.f32 "         \
                 "{%0,%1,%2,%3}, {%4,%5,%6,%7}, {%8,%9}, {%0,%1,%2,%3};"      \
                 : "+f"((d)[0]), "+f"((d)[1]), "+f"((d)[2]), "+f"((d)[3])     \
                 : "r"(a0), "r"(a1), "r"(a2), "r"(a3), "r"(b0), "r"(b1))

__device__ __forceinline__ uint32_t sw128(uint32_t off) { return off ^ ((off >> 3) & 0x70); }

// ---------------------------------------------------------------------------
// LN1 + patchify -> fp16 hi/lo A [2048][2048] row-major, k = (p0*8+p1)*32+c
// ---------------------------------------------------------------------------
__global__ __launch_bounds__(256)
void ln1_kernel(const float* __restrict__ x, const float* __restrict__ sc,
                const float* __restrict__ bi)
{
    int lane = threadIdx.x & 31;
    int warp = threadIdx.x >> 5;
    int pix  = blockIdx.x * 8 + warp;
    float v  = x[pix * 32 + lane];
    float su = v, sq = v * v;
#pragma unroll
    for (int off = 16; off; off >>= 1) {
        su += __shfl_xor_sync(0xffffffffu, su, off);
        sq += __shfl_xor_sync(0xffffffffu, sq, off);
    }
    float mu  = su * (1.f / 32.f);
    float var = sq * (1.f / 32.f) - mu * mu;
    float y   = (v - mu) * rsqrtf(var + 1e-6f) * sc[lane] + bi[lane];
    int b = pix >> 16, h = (pix >> 8) & 255, w = pix & 255;
    int row = b * 1024 + (h >> 3) * 32 + (w >> 3);
    int idx = row * K1 + ((h & 7) * 8 + (w & 7)) * 32 + lane;
    __half hi = __float2half(y);
    g_Ah[idx] = hi;
    g_Al[idx] = __float2half(y - __half2float(hi));
}

// ---------------------------------------------------------------------------
// Transpose + fp16 convert: fp32 [K,N] -> fp16 [N,K]; z selects matrix.
// ---------------------------------------------------------------------------
__global__ __launch_bounds__(256)
void wconv_t(const float* __restrict__ W0, const float* __restrict__ W1,
             const float* __restrict__ W2,
             __half* __restrict__ O0, __half* __restrict__ O1, __half* __restrict__ O2,
             int K, int N)
{
    const int z = blockIdx.z;
    const float* W = (z == 0) ? W0 : (z == 1) ? W1 : W2;
    __half* O      = (z == 0) ? O0 : (z == 1) ? O1 : O2;

    __shared__ float t[64][33];
    int kb = blockIdx.y * 64, nb = blockIdx.x * 32;
    int tx = threadIdx.x & 31, ty = threadIdx.x >> 5;
#pragma unroll
    for (int i = 0; i < 8; i++)
        t[ty + 8 * i][tx] = W[(size_t)(kb + ty + 8 * i) * N + nb + tx];
    __syncthreads();
#pragma unroll
    for (int i = 0; i < 4; i++) {
        int n = ty * 4 + i;
        __half2 h = __floats2half2_rn(t[tx * 2][n], t[tx * 2 + 1][n]);
        *(__half2*)&O[(size_t)(nb + n) * K + kb + tx * 2] = h;
    }
}

// ---------------------------------------------------------------------------
// 2-term fp16 HGEMM, 512 threads / 16 warps, warp tile 64x32:
//   C = (Ah+Al)*B^T + bias.  CTA 128x256, BK=64, 3 stages.
//   EPI==0: C row-major [M,N] (+bias), z selects {q,k,v}
//   EPI==1: scatter into final [B,H,W,C] + bias + residual X
// ---------------------------------------------------------------------------
template <int EPI>
__global__ __launch_bounds__(512, 1)
void hgemm(const __half* __restrict__ Ah, const __half* __restrict__ Al,
           const __half* __restrict__ B0, const __half* __restrict__ B1,
           const __half* __restrict__ B2,
           const float* __restrict__ bi0, const float* __restrict__ bi1,
           const float* __restrict__ bi2,
           float* __restrict__ C0, float* __restrict__ C1, float* __restrict__ C2,
           const float* __restrict__ X, int K, int N)
{
    extern __shared__ char smem_raw[];
    const uint32_t tiles = smem_u32(smem_raw);
    const int z = blockIdx.z;
    const __half* Bp  = (z == 0) ? B0 : (z == 1) ? B1 : B2;
    const float* bias = (z == 0) ? bi0 : (z == 1) ? bi1 : bi2;
    float* C          = (z == 0) ? C0 : (z == 1) ? C1 : C2;

    const int tid  = threadIdx.x;
    const int w    = tid >> 5;
    const int lane = tid & 31;
    const int rowBase = blockIdx.y * TM;
    const int colBase = blockIdx.x * TN;
    const int NC = K / BK;

    auto load_stage = [&](int c, int s) {
        uint32_t base = tiles + (uint32_t)s * STAGE_B;
        int k0 = c * BK;
#pragma unroll
        for (int i = 0; i < 2; i++) {
            int q = tid + 512 * i;
            int row = q >> 3, seg = q & 7;
            uint32_t so = sw128((uint32_t)(row * 128 + seg * 16));
            size_t go = (size_t)(rowBase + row) * K + k0 + seg * 8;
            cpa16(base + SA_H + so, Ah + go);
            cpa16(base + SA_L + so, Al + go);
        }
#pragma unroll
        for (int i = 0; i < 4; i++) {
            int q = tid + 512 * i;
            int row = q >> 3, seg = q & 7;
            uint32_t so = sw128((uint32_t)(row * 128 + seg * 16));
            cpa16(base + SB + so, Bp + (size_t)(colBase + row) * K + k0 + seg * 8);
        }
        CP_COMMIT();
    };

    const int mw = (w >> 3) * 64;        // 0 / 64
    const int nw = (w & 7) * 32;         // 0..224
    const int lr = lane & 15;
    const int lh = (lane >> 4) * 8;
    const uint32_t xr = (uint32_t)(lane & 7) << 4;

    float acc[4][4][4];
#pragma unroll
    for (int mi = 0; mi < 4; mi++)
#pragma unroll
        for (int nt = 0; nt < 4; nt++)
#pragma unroll
            for (int e = 0; e < 4; e++) acc[mi][nt][e] = 0.f;

    load_stage(0, 0);
    load_stage(1, 1);

    for (int c = 0; c < NC; c++) {
        if (c + 2 < NC) { CP_WAIT(1); } else { CP_WAIT(0); }
        __syncthreads();
        if (c + 2 < NC) load_stage(c + 2, (c + 2) % 3);

        uint32_t sbase = tiles + (uint32_t)(c % 3) * STAGE_B;
        uint32_t aH[4], aL[4], aBr[2];
#pragma unroll
        for (int mi = 0; mi < 4; mi++) {
            aH[mi] = sbase + SA_H + (uint32_t)(mw + mi * 16 + lr) * 128;
            aL[mi] = sbase + SA_L + (uint32_t)(mw + mi * 16 + lr) * 128;
        }
#pragma unroll
        for (int nj = 0; nj < 2; nj++)
            aBr[nj] = sbase + SB + (uint32_t)(nw + nj * 16 + lr) * 128;

#pragma unroll
        for (int kk = 0; kk < 4; kk++) {
            uint32_t kt = ((uint32_t)(kk * 16 + lh) * 2) ^ xr;
            uint32_t b[4][2];
#pragma unroll
            for (int nj = 0; nj < 2; nj++) {
                uint32_t t0, t1, t2, t3;
                LDSM4(t0, t1, t2, t3, aBr[nj] + kt);
                b[nj * 2 + 0][0] = t0; b[nj * 2 + 0][1] = t2;
                b[nj * 2 + 1][0] = t1; b[nj * 2 + 1][1] = t3;
            }
            uint32_t a[4][4];
#pragma unroll
            for (int mi = 0; mi < 4; mi++)
                LDSM4(a[mi][0], a[mi][1], a[mi][2], a[mi][3], aH[mi] + kt);
#pragma unroll
            for (int mi = 0; mi < 4; mi++)
#pragma unroll
                for (int nt = 0; nt < 4; nt++)
                    MMAH(acc[mi][nt], a[mi][0], a[mi][1], a[mi][2], a[mi][3],
                         b[nt][0], b[nt][1]);
#pragma unroll
            for (int mi = 0; mi < 4; mi++)
                LDSM4(a[mi][0], a[mi][1], a[mi][2], a[mi][3], aL[mi] + kt);
#pragma unroll
            for (int mi = 0; mi < 4; mi++)
#pragma unroll
                for (int nt = 0; nt < 4; nt++)
                    MMAH(acc[mi][nt], a[mi][0], a[mi][1], a[mi][2], a[mi][3],
                         b[nt][0], b[nt][1]);
        }
    }

    // epilogue
#pragma unroll
    for (int mi = 0; mi < 4; mi++) {
#pragma unroll
        for (int nt = 0; nt < 4; nt++) {
            int r0 = rowBase + mw + mi * 16 + (lane >> 2);
            int f  = colBase + nw + nt * 8 + (lane & 3) * 2;
            float b0 = bias[f], b1 = bias[f + 1];
            if (EPI == 0) {
                C[(size_t)r0 * N + f]           = acc[mi][nt][0] + b0;
                C[(size_t)r0 * N + f + 1]       = acc[mi][nt][1] + b1;
                C[(size_t)(r0 + 8) * N + f]     = acc[mi][nt][2] + b0;
                C[(size_t)(r0 + 8) * N + f + 1] = acc[mi][nt][3] + b1;
            } else {
#pragma unroll
                for (int e = 0; e < 4; e++) {
                    int r = r0 + (e >> 1) * 8;
                    int ff = f + (e & 1);
                    float v = acc[mi][nt][e] + ((e & 1) ? b1 : b0);
                    int b_ = r >> 10, ghgw = r & 1023;
                    int gh = ghgw >> 5, gw = ghgw & 31;
                    int p1 = ff & 7, p0 = (ff >> 3) & 7, cc = ff >> 6;
                    size_t idx = (size_t)((b_ * 256 + gh * 8 + p0) * 256 + gw * 8 + p1) * 32 + cc;
                    C[idx] = v + X[idx];
                }
            }
        }
    }
}

// ---------------------------------------------------------------------------
// fsas v2: one CTA per patch-row r (all 8 heads).
// ---------------------------------------------------------------------------
__global__ __launch_bounds__(256)
void fsas2(const float* __restrict__ ln2s, const float* __restrict__ ln2b)
{
    extern __shared__ float fs[];
    float* fq = fs;
    float* fk = fs + FS_ELEM;
    float* fv = fs + 2 * FS_ELEM;
    int tid = threadIdx.x;
    int r = blockIdx.x;
    size_t rb = (size_t)r * 16384;

    for (int i = tid; i < 16384; i += 256) {
        int head = i & 7, p = (i >> 3) & 63, c = i >> 9;
        int s = c * 577 + p * 9 + head;
        fq[s] = g_q[rb + i];
        fk[s] = g_k[rb + i];
        fv[s] = g_v[rb + i];
    }
    __syncthreads();

    int head = tid >> 5, c = tid & 31;
    const float* q0 = fq + c * 577 + head;
    const float* k0 = fk + c * 577 + head;
    float out[64];
#pragma unroll
    for (int p = 0; p < 64; p++) out[p] = 0.f;

#pragma unroll
    for (int a0 = 0; a0 < 8; a0++) {
        float qv[8];
#pragma unroll
        for (int a1 = 0; a1 < 8; a1++) qv[a1] = q0[(a0 * 8 + a1) * 9];
#pragma unroll
        for (int p0 = 0; p0 < 8; p0++) {
            int kr = (p0 - a0) & 7;
            float kv[8];
#pragma unroll
            for (int t = 0; t < 8; t++) kv[t] = k0[(kr * 8 + t) * 9];
#pragma unroll
            for (int a1 = 0; a1 < 8; a1++) {
                float qa = qv[a1];
#pragma unroll
                for (int p1 = 0; p1 < 8; p1++)
                    out[p0 * 8 + p1] += qa * kv[(p1 - a1) & 7];
            }
        }
    }
    __syncthreads();

    float sc = ln2s[c], sb = ln2b[c];
    __half* sgh = (__half*)fq;
    __half* sgl = sgh + 64 * 264;
    const float* v0 = fv + c * 577 + head;

#pragma unroll
    for (int p = 0; p < 64; p++) {
        float s = out[p], s2 = out[p] * out[p];
#pragma unroll
        for (int o = 16; o; o >>= 1) {
            s  += __shfl_xor_sync(0xffffffffu, s,  o);
            s2 += __shfl_xor_sync(0xffffffffu, s2, o);
        }
        float mu  = s * (1.f / 32.f);
        float var = s2 * (1.f / 32.f) - mu * mu;
        float val = (out[p] - mu) * rsqrtf(var + 1e-6f) * sc + sb;
        val *= v0[p * 9];
        __half hi = __float2half(val);
        __half lo = __float2half(val - __half2float(hi));
        sgh[p * 264 + head * 32 + c] = hi;
        sgl[p * 264 + head * 32 + c] = lo;
    }
    __syncthreads();

    uint32_t* gh = (uint32_t*)g_oh;
    uint32_t* gl = (uint32_t*)g_ol;
    size_t rb2 = (size_t)r * 8192;
    for (int i = tid; i < 8192; i += 256) {
        int p = i >> 7, cl = i & 127;
        gh[rb2 + i] = *(uint32_t*)&sgh[p * 264 + cl * 2];
        gl[rb2 + i] = *(uint32_t*)&sgl[p * 264 + cl * 2];
    }
}

// ---------------------------------------------------------------------------
extern "C" void kernel_launch(void* const* d_in, const int* in_sizes, int n_in,
                              void* d_out, int out_size)
{
    const float* x    = (const float*)d_in[0];
    const float* ln1s = (const float*)d_in[1];
    const float* ln1b = (const float*)d_in[2];
    const float* Wq   = (const float*)d_in[3];
    const float* bq   = (const float*)d_in[4];
    const float* Wk   = (const float*)d_in[5];
    const float* bk   = (const float*)d_in[6];
    const float* Wv   = (const float*)d_in[7];
    const float* bv   = (const float*)d_in[8];
    const float* ln2s = (const float*)d_in[9];
    const float* ln2b = (const float*)d_in[10];
    const float* Wo   = (const float*)d_in[11];
    const float* bo   = (const float*)d_in[12];
    float* out = (float*)d_out;

    cudaFuncSetAttribute(hgemm<0>, cudaFuncAttributeMaxDynamicSharedMemorySize, GSMEM);
    cudaFuncSetAttribute(hgemm<1>, cudaFuncAttributeMaxDynamicSharedMemorySize, GSMEM);
    cudaFuncSetAttribute(fsas2,    cudaFuncAttributeMaxDynamicSharedMemorySize, FS_SMEM);

    __half *pAh, *pAl, *pWq, *pWk, *pWv, *pWo, *poh, *pol;
    float *pq, *pk, *pv;
    cudaGetSymbolAddress((void**)&pAh, g_Ah); cudaGetSymbolAddress((void**)&pAl, g_Al);
    cudaGetSymbolAddress((void**)&pWq, g_Wq); cudaGetSymbolAddress((void**)&pWk, g_Wk);
    cudaGetSymbolAddress((void**)&pWv, g_Wv); cudaGetSymbolAddress((void**)&pWo, g_Wo);
    cudaGetSymbolAddress((void**)&poh, g_oh); cudaGetSymbolAddress((void**)&pol, g_ol);
    cudaGetSymbolAddress((void**)&pq, g_q);
    cudaGetSymbolAddress((void**)&pk, g_k);
    cudaGetSymbolAddress((void**)&pv, g_v);

    // 1) LN1 + patchify
    ln1_kernel<<<(Bn * 256 * 256) / 8, 256>>>(x, ln1s, ln1b);

    // 2) weight transpose + fp16 convert (QKV merged via z, then Wo)
    dim3 gwq(F1 / 32, K1 / 64, 3);
    wconv_t<<<gwq, 256>>>(Wq, Wk, Wv, pWq, pWk, pWv, K1, F1);
    dim3 gwo(N2 / 32, K2 / 64, 1);
    wconv_t<<<gwo, 256>>>(Wo, Wo, Wo, pWo, pWo, pWo, K2, N2);

    // 3) QKV projections (merged, z selects matrix), row-major outputs
    dim3 g1(F1 / TN, Mrows / TM, 3);
    hgemm<0><<<g1, 512, GSMEM>>>(pAh, pAl, pWq, pWk, pWv, bq, bk, bv,
                                 pq, pk, pv, nullptr, K1, F1);

    // 4) circular conv + LN2 + gate -> fp16 hi/lo im2col
    fsas2<<<Mrows, 256, FS_SMEM>>>(ln2s, ln2b);

    // 5) output projection + bias + residual
    dim3 g2(N2 / TN, Mrows / TM, 1);
    hgemm<1><<<g2, 512, GSMEM>>>(poh, pol, pWo, pWo, pWo, bo, bo, bo,
                                 out, out, out, x, K2, N2);
}